// round 5
// baseline (speedup 1.0000x reference)
#include <cuda_runtime.h>
#include <math.h>

#define DIN 128
#define DQK 64
#define NEGM (-1000000.0f)
#define MARGIN 65536.0f

// smem float offsets
#define OFF_W 0        // 8192  : Wq then Wk (Wk persists for fallback)
#define OFF_X 8192     // 4224  : [32][132] input rows (query, then key_off)
#define OFF_Q 12416    // 2176  : q [32][68]
#define OFF_K 14592    // 2176  : k_off [32cols][68]
#define OFF_RED 16768  // 256
#define OFF_QN 17024   // 32
#define OFF_T 17056    // 32    : b-rowmax, then threshold u
#define OFF_FND 17088  // 32 ints
#define OFF_FLG 17120  // 8 (ints: [0]=all, [1]=keynorm2 max)
#define OFF_MISC 17128 // 8 floats: [0]=Fk, [1]=nbk
#define OFF_PTR 17136  // 68 ints
#define OFF_WT 17204   // 132 : Wk*q for fallback
#define SMEM_FLOATS 17344

__device__ __forceinline__ float blockReduceSum256(float v, float* scr, int tid) {
  scr[tid] = v;
  __syncthreads();
  for (int s = 128; s > 0; s >>= 1) {
    if (tid < s) scr[tid] = scr[tid] + scr[tid + s];
    __syncthreads();
  }
  float r = scr[0];
  __syncthreads();
  return r;
}
__device__ __forceinline__ float blockReduceMax256(float v, float* scr, int tid) {
  scr[tid] = v;
  __syncthreads();
  for (int s = 128; s > 0; s >>= 1) {
    if (tid < s) scr[tid] = fmaxf(scr[tid], scr[tid + s]);
    __syncthreads();
  }
  float r = scr[0];
  __syncthreads();
  return r;
}

__global__ __launch_bounds__(256) void fused_kernel(
    const float* __restrict__ query, const float* __restrict__ key,
    const float* __restrict__ value, const float* __restrict__ bmat,
    const int* __restrict__ ptr, const float* __restrict__ Wq,
    const float* __restrict__ bq, const float* __restrict__ Wk,
    const float* __restrict__ bk, const float* __restrict__ Wv,
    const float* __restrict__ bv, float* __restrict__ out, int n, int g) {
  extern __shared__ float sm[];
  float* sW = sm + OFF_W;
  float* sX = sm + OFF_X;
  float* sQ = sm + OFF_Q;
  float* sK = sm + OFF_K;
  float* sRed = sm + OFF_RED;
  float* sQn = sm + OFF_QN;
  float* sT = sm + OFF_T;
  int* sFnd = (int*)(sm + OFF_FND);
  int* sFlg = (int*)(sm + OFF_FLG);
  float* sMisc = sm + OFF_MISC;
  int* sPtr = (int*)(sm + OFF_PTR);
  float* sWt = sm + OFF_WT;

  int tid = threadIdx.x;
  int r0 = blockIdx.x * 32;
  if (r0 >= n) return;
  int nr = min(32, n - r0);

  for (int i = tid; i <= g; i += 256) sPtr[i] = ptr[i];
  if (tid == 0) { sFlg[0] = 0; sFlg[1] = 0; }
  if (tid < 32) sFnd[tid] = (tid >= nr) ? 1 : 0;
  __syncthreads();

  // segment of first row
  int seg = 0;
  for (int i = 1; i < g; i++)
    if (sPtr[i] <= r0) seg = i;
  int s0 = sPtr[seg], s1 = sPtr[seg + 1];
  bool aligned = (r0 >= s0) && (r0 + nr <= s1);
  int c0 = -1;
  if (aligned) {
    if (s1 + 32 <= n) c0 = s1;
    else if (s0 >= 32) c0 = s0 - 32;
  }

  int r = tid >> 3, cg = tid & 7;

  // ---------- phase 1: q = query@Wq + bq for own rows ----------
  {
    const float4* W4 = (const float4*)Wq;
    float4* sW4 = (float4*)sW;
#pragma unroll
    for (int i = tid; i < 2048; i += 256) sW4[i] = W4[i];
    for (int i = tid; i < 1024; i += 256) {
      int rr = i >> 5, c4 = i & 31;
      float4 v = make_float4(0.f, 0.f, 0.f, 0.f);
      if (r0 + rr < n) v = ((const float4*)(query + (size_t)(r0 + rr) * DIN))[c4];
      ((float4*)sX)[rr * 33 + c4] = v;
    }
    __syncthreads();
    float acc[8];
#pragma unroll
    for (int j = 0; j < 8; j++) acc[j] = bq[cg * 8 + j];
    const float* xr = sX + r * 132;
#pragma unroll 4
    for (int kk = 0; kk < DIN; kk++) {
      float x = xr[kk];
      float4 w0 = *(const float4*)(sW + kk * DQK + cg * 8);
      float4 w1 = *(const float4*)(sW + kk * DQK + cg * 8 + 4);
      acc[0] = fmaf(x, w0.x, acc[0]);
      acc[1] = fmaf(x, w0.y, acc[1]);
      acc[2] = fmaf(x, w0.z, acc[2]);
      acc[3] = fmaf(x, w0.w, acc[3]);
      acc[4] = fmaf(x, w1.x, acc[4]);
      acc[5] = fmaf(x, w1.y, acc[5]);
      acc[6] = fmaf(x, w1.z, acc[6]);
      acc[7] = fmaf(x, w1.w, acc[7]);
    }
#pragma unroll
    for (int j = 0; j < 8; j++) sQ[r * 68 + cg * 8 + j] = acc[j];
    float ss = 0.f;
#pragma unroll
    for (int j = 0; j < 8; j++) ss = fmaf(acc[j], acc[j], ss);
    ss += __shfl_xor_sync(0xffffffffu, ss, 1);
    ss += __shfl_xor_sync(0xffffffffu, ss, 2);
    ss += __shfl_xor_sync(0xffffffffu, ss, 4);
    if (cg == 0) sQn[r] = sqrtf(ss);
  }
  __syncthreads();  // q done; sW/sX reusable

  // ---------- phase 2: load Wk (keep!), key_off rows; Fk, |bk| ----------
  float wsum = 0.f;
  {
    const float4* W4 = (const float4*)Wk;
    float4* sW4 = (float4*)sW;
#pragma unroll
    for (int i = tid; i < 2048; i += 256) {
      float4 v = W4[i];
      sW4[i] = v;
      wsum = fmaf(v.x, v.x, fmaf(v.y, v.y, fmaf(v.z, v.z, fmaf(v.w, v.w, wsum))));
    }
    if (c0 >= 0) {
      for (int i = tid; i < 1024; i += 256) {
        int rr = i >> 5, c4 = i & 31;
        ((float4*)sX)[rr * 33 + c4] = ((const float4*)(key + (size_t)(c0 + rr) * DIN))[c4];
      }
    }
  }
  __syncthreads();
  {
    float f2 = blockReduceSum256(wsum, sRed, tid);
    float b2 = blockReduceSum256((tid < DQK) ? bk[tid] * bk[tid] : 0.f, sRed, tid);
    if (tid == 0) {
      sMisc[0] = sqrtf(f2);
      sMisc[1] = sqrtf(b2);
    }
  }
  // k_off GEMM: "row" index = off-col index
  if (c0 >= 0) {
    float acc[8];
#pragma unroll
    for (int j = 0; j < 8; j++) acc[j] = bk[cg * 8 + j];
    const float* xr = sX + r * 132;
#pragma unroll 4
    for (int kk = 0; kk < DIN; kk++) {
      float x = xr[kk];
      float4 w0 = *(const float4*)(sW + kk * DQK + cg * 8);
      float4 w1 = *(const float4*)(sW + kk * DQK + cg * 8 + 4);
      acc[0] = fmaf(x, w0.x, acc[0]);
      acc[1] = fmaf(x, w0.y, acc[1]);
      acc[2] = fmaf(x, w0.z, acc[2]);
      acc[3] = fmaf(x, w0.w, acc[3]);
      acc[4] = fmaf(x, w1.x, acc[4]);
      acc[5] = fmaf(x, w1.y, acc[5]);
      acc[6] = fmaf(x, w1.z, acc[6]);
      acc[7] = fmaf(x, w1.w, acc[7]);
    }
#pragma unroll
    for (int j = 0; j < 8; j++) sK[r * 68 + cg * 8 + j] = acc[j];
  }

  if (c0 >= 0) {
    // ---------- phase 3: max in-block ||key_c|| ----------
    {
      int w = tid >> 5, lane = tid & 31;
      float mx = 0.f;
      for (int c = s0 + w; c < s1; c += 8) {
        const float* kr = key + (size_t)c * DIN;
        float s = 0.f;
#pragma unroll
        for (int j = 0; j < 4; j++) {
          float v = kr[lane + 32 * j];
          s = fmaf(v, v, s);
        }
        s += __shfl_xor_sync(0xffffffffu, s, 16);
        s += __shfl_xor_sync(0xffffffffu, s, 8);
        s += __shfl_xor_sync(0xffffffffu, s, 4);
        s += __shfl_xor_sync(0xffffffffu, s, 2);
        s += __shfl_xor_sync(0xffffffffu, s, 1);
        mx = fmaxf(mx, s);
      }
      if (lane == 0 && mx > 0.f) atomicMax(&sFlg[1], __float_as_int(mx));
    }
    // ---------- phase 4: per-row in-block b max ----------
    {
      int w = tid >> 5, lane = tid & 31;
      for (int rr = w * 4; rr < w * 4 + 4; rr++) {
        if (rr < nr) {
          float mx = -3.0e38f;
          const float* brow = bmat + (size_t)(r0 + rr) * n;
          for (int c = s0 + lane; c < s1; c += 32) mx = fmaxf(mx, brow[c]);
          mx = fmaxf(mx, __shfl_xor_sync(0xffffffffu, mx, 16));
          mx = fmaxf(mx, __shfl_xor_sync(0xffffffffu, mx, 8));
          mx = fmaxf(mx, __shfl_xor_sync(0xffffffffu, mx, 4));
          mx = fmaxf(mx, __shfl_xor_sync(0xffffffffu, mx, 2));
          mx = fmaxf(mx, __shfl_xor_sync(0xffffffffu, mx, 1));
          if (lane == 0) sT[rr] = mx;
        }
      }
    }
    __syncthreads();
    // ---------- phase 5: thresholds ----------
    if (tid < 32) {
      float kb = sqrtf(__int_as_float(sFlg[1])) * sMisc[0] + sMisc[1];  // ||key||max*||Wk||_F + ||bk||
      float T = sQn[tid] * kb * 0.125f + sT[tid] + MARGIN;
      sT[tid] = -1.0e-6f * T;  // proven if dot/8 + b < sT[r]
    }
    __syncthreads();
    // ---------- phase 6: test 32 off-block columns per row ----------
    {
      if (r < nr) {
        float dot[4] = {0.f, 0.f, 0.f, 0.f};
        const float* qrow = sQ + r * 68;
#pragma unroll 4
        for (int kk = 0; kk < DQK; kk++) {
          float qv = qrow[kk];
#pragma unroll
          for (int j = 0; j < 4; j++)
            dot[j] = fmaf(qv, sK[(cg + 8 * j) * 68 + kk], dot[j]);
        }
        const float* brow = bmat + (size_t)(r0 + r) * n + c0;
        float u = sT[r];
        int f = 0;
#pragma unroll
        for (int j = 0; j < 4; j++)
          f |= (dot[j] * 0.125f + brow[cg + 8 * j] < u) ? 1 : 0;
        if (f) sFnd[r] = 1;  // benign race, same value
      }
    }
    __syncthreads();
  }

  if (tid < 32) {
    unsigned bal = __ballot_sync(0xffffffffu, sFnd[tid] != 0);
    if (tid == 0) sFlg[0] = (bal == 0xffffffffu) ? 1 : 0;
  }
  __syncthreads();

  // write zeros for proven rows
  {
    float4 z = make_float4(0.f, 0.f, 0.f, 0.f);
    float4* o4 = (float4*)(out + (size_t)r0 * DQK);
    for (int i = tid; i < 512; i += 256) {
      int rr = i >> 4;
      if (rr < nr && sFnd[rr]) o4[i] = z;
    }
  }
  if (sFlg[0]) return;  // all proven

  // ================= honest fallback for unproven rows ==================
  // dot(q_r, k_c) = (Wk q_r) . key_c + q_r . bk    (sW still holds Wk)
  for (int rr = 0; rr < nr; rr++) {
    if (sFnd[rr]) continue;
    int row = r0 + rr;
    int sg = 0;
    for (int i = 1; i < g; i++)
      if (sPtr[i] <= row) sg = i;
    int rs0 = sPtr[sg], rs1 = sPtr[sg + 1];
    const float* qrow = sQ + rr * 68;
    const float* brow = bmat + (size_t)row * n;

    if (tid < DIN) {
      float s = 0.f;
      for (int d = 0; d < DQK; d++) s = fmaf(sW[tid * DQK + d], qrow[d], s);
      sWt[tid] = s;
    }
    float cq = blockReduceSum256((tid < DQK) ? bk[tid] * qrow[tid] : 0.f, sRed, tid);

    float m = -3.0e38f;
    for (int c = tid; c < n; c += 256) {
      float dot = cq;
      const float* kr = key + (size_t)c * DIN;
      for (int d = 0; d < DIN; d++) dot = fmaf(sWt[d], kr[d], dot);
      float s = dot * 0.125f + brow[c];
      if (!(c >= rs0 && c < rs1)) s *= NEGM;
      m = fmaxf(m, s);
    }
    m = blockReduceMax256(m, sRed, tid);

    float dsum = 0.f;
    for (int c = tid; c < n; c += 256) {
      float dot = cq;
      const float* kr = key + (size_t)c * DIN;
      for (int d = 0; d < DIN; d++) dot = fmaf(sWt[d], kr[d], dot);
      float s = dot * 0.125f + brow[c];
      if (!(c >= rs0 && c < rs1)) s *= NEGM;
      dsum += expf(s - m);
    }
    float D = blockReduceSum256(dsum, sRed, tid);

    float o = 0.f;
    for (int base = rs0; base < rs1; base += 256) {
      int c = base + tid;
      float w = 0.f;
      if (c < rs1) {
        float dot = cq;
        const float* kr = key + (size_t)c * DIN;
        for (int d = 0; d < DIN; d++) dot = fmaf(sWt[d], kr[d], dot);
        float s = dot * 0.125f + brow[c];
        w = expf(s - m);
      }
      sRed[tid] = w;
      __syncthreads();
      int lim = min(256, rs1 - base);
      if (tid < DQK) {
        for (int cc = 0; cc < lim; cc++) {
          int c2 = base + cc;
          float vv = bv[tid];
          const float* vr = value + (size_t)c2 * DIN;
          for (int kk = 0; kk < DIN; kk++) vv = fmaf(vr[kk], Wv[kk * DQK + tid], vv);
          o = fmaf(sRed[cc], vv, o);
        }
      }
      __syncthreads();
    }
    if (tid < DQK) out[(size_t)row * DQK + tid] = o / D;
    __syncthreads();
  }
}

extern "C" void kernel_launch(void* const* d_in, const int* in_sizes, int n_in,
                              void* d_out, int out_size) {
  const float* query = (const float*)d_in[0];
  const float* key = (const float*)d_in[1];
  const float* value = (const float*)d_in[2];
  const float* bmat = (const float*)d_in[3];
  const int* ptr = (const int*)d_in[4];
  const float* Wq = (const float*)d_in[5];
  const float* bq = (const float*)d_in[6];
  const float* Wk = (const float*)d_in[7];
  const float* bk = (const float*)d_in[8];
  const float* Wv = (const float*)d_in[9];
  const float* bv = (const float*)d_in[10];
  float* out = (float*)d_out;

  int n = in_sizes[0] / DIN;
  int g = in_sizes[4] - 1;
  int nblk = (n + 31) / 32;

  size_t smB = (size_t)SMEM_FLOATS * sizeof(float);
  cudaFuncSetAttribute(fused_kernel, cudaFuncAttributeMaxDynamicSharedMemorySize, (int)smB);
  fused_kernel<<<nblk, 256, smB>>>(query, key, value, bmat, ptr, Wq, bq, Wk, bk,
                                   Wv, bv, out, n, g);
}

// round 15
// speedup vs baseline: 1.1960x; 1.1960x over previous
#include <cuda_runtime.h>
#include <math.h>

#define DIN 128
#define DQK 64
#define NEGM (-1000000.0f)
#define MARGIN 65536.0f

// smem float offsets
#define OFF_W 0        // 8192  : Wq then Wk (Wk persists for fallback)
#define OFF_X 8192     // 4224  : [32][132] input rows (query, then key_off)
#define OFF_Q 12416    // 2176  : q [32][68]
#define OFF_K 14592    // 2176  : k_off [32cols][68]
#define OFF_RED 16768  // 256   : fallback reduces
#define OFF_QN 17024   // 32
#define OFF_T 17056    // 32    : b-rowmax, then threshold u
#define OFF_FND 17088  // 32 ints
#define OFF_FLG 17120  // 8 ints: [0]=all-proven, [1]=max in-block |key|^2 (bits)
#define OFF_MISC 17128 // 8 floats: [0]=sum Wk^2, [1]=sum bk^2
#define OFF_PTR 17136  // 68 ints
#define OFF_WT 17204   // 132 : Wk*q for fallback
#define SMEM_FLOATS 17344

__device__ __forceinline__ float blockReduceSum256(float v, float* scr, int tid) {
  scr[tid] = v;
  __syncthreads();
  for (int s = 128; s > 0; s >>= 1) {
    if (tid < s) scr[tid] = scr[tid] + scr[tid + s];
    __syncthreads();
  }
  float r = scr[0];
  __syncthreads();
  return r;
}
__device__ __forceinline__ float blockReduceMax256(float v, float* scr, int tid) {
  scr[tid] = v;
  __syncthreads();
  for (int s = 128; s > 0; s >>= 1) {
    if (tid < s) scr[tid] = fmaxf(scr[tid], scr[tid + s]);
    __syncthreads();
  }
  float r = scr[0];
  __syncthreads();
  return r;
}

__global__ __launch_bounds__(256, 2) void fused_kernel(
    const float* __restrict__ query, const float* __restrict__ key,
    const float* __restrict__ value, const float* __restrict__ bmat,
    const int* __restrict__ ptr, const float* __restrict__ Wq,
    const float* __restrict__ bq, const float* __restrict__ Wk,
    const float* __restrict__ bk, const float* __restrict__ Wv,
    const float* __restrict__ bv, float* __restrict__ out, int n, int g) {
  extern __shared__ float sm[];
  float* sW = sm + OFF_W;
  float* sX = sm + OFF_X;
  float* sQ = sm + OFF_Q;
  float* sK = sm + OFF_K;
  float* sRed = sm + OFF_RED;
  float* sQn = sm + OFF_QN;
  float* sT = sm + OFF_T;
  int* sFnd = (int*)(sm + OFF_FND);
  int* sFlg = (int*)(sm + OFF_FLG);
  float* sMisc = sm + OFF_MISC;
  int* sPtr = (int*)(sm + OFF_PTR);
  float* sWt = sm + OFF_WT;

  int tid = threadIdx.x;
  int lane = tid & 31, wrp = tid >> 5;
  int r0 = blockIdx.x * 32;
  if (r0 >= n) return;
  int nr = min(32, n - r0);

  for (int i = tid; i <= g; i += 256) sPtr[i] = ptr[i];
  if (tid == 0) {
    sFlg[0] = 0;
    sFlg[1] = 0;
    sMisc[0] = 0.f;
    sMisc[1] = 0.f;
  }
  if (tid < 32) sFnd[tid] = (tid >= nr) ? 1 : 0;

  int r = tid >> 3, cg = tid & 7;

  // ---------- phase 1: q = query@Wq + bq for own rows ----------
  {
    const float4* W4 = (const float4*)Wq;
    float4* sW4 = (float4*)sW;
#pragma unroll
    for (int i = tid; i < 2048; i += 256) sW4[i] = W4[i];
    for (int i = tid; i < 1024; i += 256) {
      int rr = i >> 5, c4 = i & 31;
      float4 v = make_float4(0.f, 0.f, 0.f, 0.f);
      if (r0 + rr < n) v = ((const float4*)(query + (size_t)(r0 + rr) * DIN))[c4];
      ((float4*)sX)[rr * 33 + c4] = v;
    }
    __syncthreads();
    float acc[8];
#pragma unroll
    for (int j = 0; j < 8; j++) acc[j] = bq[cg * 8 + j];
    const float* xr = sX + r * 132;
#pragma unroll 4
    for (int kk = 0; kk < DIN; kk++) {
      float x = xr[kk];
      float4 w0 = *(const float4*)(sW + kk * DQK + cg * 8);
      float4 w1 = *(const float4*)(sW + kk * DQK + cg * 8 + 4);
      acc[0] = fmaf(x, w0.x, acc[0]);
      acc[1] = fmaf(x, w0.y, acc[1]);
      acc[2] = fmaf(x, w0.z, acc[2]);
      acc[3] = fmaf(x, w0.w, acc[3]);
      acc[4] = fmaf(x, w1.x, acc[4]);
      acc[5] = fmaf(x, w1.y, acc[5]);
      acc[6] = fmaf(x, w1.z, acc[6]);
      acc[7] = fmaf(x, w1.w, acc[7]);
    }
#pragma unroll
    for (int j = 0; j < 8; j++) sQ[r * 68 + cg * 8 + j] = acc[j];
    float ss = 0.f;
#pragma unroll
    for (int j = 0; j < 8; j++) ss = fmaf(acc[j], acc[j], ss);
    ss += __shfl_xor_sync(0xffffffffu, ss, 1);
    ss += __shfl_xor_sync(0xffffffffu, ss, 2);
    ss += __shfl_xor_sync(0xffffffffu, ss, 4);
    if (cg == 0) sQn[r] = sqrtf(ss);
  }
  __syncthreads();  // q done; sW/sX reusable

  // segment of first row (sPtr valid after syncs)
  int seg = 0;
  for (int i = 1; i < g; i++)
    if (sPtr[i] <= r0) seg = i;
  int s0 = sPtr[seg], s1 = sPtr[seg + 1];
  bool aligned = (r0 >= s0) && (r0 + nr <= s1);
  int c0 = -1;
  if (aligned) {
    if (s1 + 32 <= n) c0 = s1;
    else if (s0 >= 32) c0 = s0 - 32;
  }

  // ---------- phase 2: load Wk (fold F-norm), bk norm, key_off rows ----------
  {
    const float4* W4 = (const float4*)Wk;
    float4* sW4 = (float4*)sW;
    float wsum = 0.f;
#pragma unroll
    for (int i = tid; i < 2048; i += 256) {
      float4 v = W4[i];
      sW4[i] = v;
      wsum = fmaf(v.x, v.x, fmaf(v.y, v.y, fmaf(v.z, v.z, fmaf(v.w, v.w, wsum))));
    }
#pragma unroll
    for (int o = 16; o > 0; o >>= 1) wsum += __shfl_xor_sync(0xffffffffu, wsum, o);
    if (lane == 0) atomicAdd(&sMisc[0], wsum);
    if (tid < DQK) {
      float b2 = bk[tid] * bk[tid];
#pragma unroll
      for (int o = 16; o > 0; o >>= 1) b2 += __shfl_xor_sync(0xffffffffu, b2, o);
      if (lane == 0) atomicAdd(&sMisc[1], b2);
    }
    if (c0 >= 0) {
      for (int i = tid; i < 1024; i += 256) {
        int rr = i >> 5, c4 = i & 31;
        ((float4*)sX)[rr * 33 + c4] =
            ((const float4*)(key + (size_t)(c0 + rr) * DIN))[c4];
      }
    }
  }
  __syncthreads();

  // ---------- phase 2 compute: k_off = key_off@Wk + bk ----------
  if (c0 >= 0) {
    float acc[8];
#pragma unroll
    for (int j = 0; j < 8; j++) acc[j] = bk[cg * 8 + j];
    const float* xr = sX + r * 132;
#pragma unroll 4
    for (int kk = 0; kk < DIN; kk++) {
      float x = xr[kk];
      float4 w0 = *(const float4*)(sW + kk * DQK + cg * 8);
      float4 w1 = *(const float4*)(sW + kk * DQK + cg * 8 + 4);
      acc[0] = fmaf(x, w0.x, acc[0]);
      acc[1] = fmaf(x, w0.y, acc[1]);
      acc[2] = fmaf(x, w0.z, acc[2]);
      acc[3] = fmaf(x, w0.w, acc[3]);
      acc[4] = fmaf(x, w1.x, acc[4]);
      acc[5] = fmaf(x, w1.y, acc[5]);
      acc[6] = fmaf(x, w1.z, acc[6]);
      acc[7] = fmaf(x, w1.w, acc[7]);
    }
#pragma unroll
    for (int j = 0; j < 8; j++) sK[r * 68 + cg * 8 + j] = acc[j];
  }

  if (c0 >= 0) {
    // ---------- phases 3+4 concurrently on disjoint warps ----------
    if (wrp < 4) {
      // warps 0-3: per-row in-block b max
      for (int rr = wrp; rr < 32; rr += 4) {
        if (rr < nr) {
          float mx = -3.0e38f;
          const float* brow = bmat + (size_t)(r0 + rr) * n;
          for (int c = s0 + lane; c < s1; c += 32) mx = fmaxf(mx, brow[c]);
#pragma unroll
          for (int o = 16; o > 0; o >>= 1)
            mx = fmaxf(mx, __shfl_xor_sync(0xffffffffu, mx, o));
          if (lane == 0) sT[rr] = mx;
        }
      }
    } else {
      // warps 4-7: max in-block ||key_c||^2
      float mx = 0.f;
      for (int c = s0 + (wrp - 4); c < s1; c += 4) {
        const float* kr = key + (size_t)c * DIN;
        float s = 0.f;
#pragma unroll
        for (int j = 0; j < 4; j++) {
          float v = kr[lane + 32 * j];
          s = fmaf(v, v, s);
        }
#pragma unroll
        for (int o = 16; o > 0; o >>= 1) s += __shfl_xor_sync(0xffffffffu, s, o);
        mx = fmaxf(mx, s);
      }
      if (lane == 0 && mx > 0.f) atomicMax(&sFlg[1], __float_as_int(mx));
    }
    __syncthreads();

    // ---------- phase 5: thresholds ----------
    if (tid < 32) {
      float kb = sqrtf(__int_as_float(sFlg[1])) * sqrtf(sMisc[0]) + sqrtf(sMisc[1]);
      float T = sQn[tid] * kb * 0.125f + sT[tid] + MARGIN;
      sT[tid] = -1.0e-6f * T;  // proven if dot/8 + b < sT[r]
    }
    __syncthreads();

    // ---------- phase 6: test 32 off-block columns per row ----------
    {
      if (r < nr) {
        float dot[4] = {0.f, 0.f, 0.f, 0.f};
        const float* qrow = sQ + r * 68;
#pragma unroll 4
        for (int kk = 0; kk < DQK; kk++) {
          float qv = qrow[kk];
#pragma unroll
          for (int j = 0; j < 4; j++)
            dot[j] = fmaf(qv, sK[(cg + 8 * j) * 68 + kk], dot[j]);
        }
        const float* brow = bmat + (size_t)(r0 + r) * n + c0;
        float u = sT[r];
        int f = 0;
#pragma unroll
        for (int j = 0; j < 4; j++)
          f |= (dot[j] * 0.125f + brow[cg + 8 * j] < u) ? 1 : 0;
        if (f) sFnd[r] = 1;  // benign race, same value
      }
    }
    __syncthreads();
  }

  if (tid < 32) {
    unsigned bal = __ballot_sync(0xffffffffu, sFnd[tid] != 0);
    if (tid == 0) sFlg[0] = (bal == 0xffffffffu) ? 1 : 0;
  }
  __syncthreads();

  // write zeros for proven rows
  {
    float4 z = make_float4(0.f, 0.f, 0.f, 0.f);
    float4* o4 = (float4*)(out + (size_t)r0 * DQK);
    for (int i = tid; i < 512; i += 256) {
      int rr = i >> 4;
      if (rr < nr && sFnd[rr]) o4[i] = z;
    }
  }
  if (sFlg[0]) return;  // all proven

  // ================= honest fallback for unproven rows ==================
  // dot(q_r, k_c) = (Wk q_r) . key_c + q_r . bk    (sW still holds Wk)
  for (int rr = 0; rr < nr; rr++) {
    if (sFnd[rr]) continue;
    int row = r0 + rr;
    int sg = 0;
    for (int i = 1; i < g; i++)
      if (sPtr[i] <= row) sg = i;
    int rs0 = sPtr[sg], rs1 = sPtr[sg + 1];
    const float* qrow = sQ + rr * 68;
    const float* brow = bmat + (size_t)row * n;

    if (tid < DIN) {
      float s = 0.f;
      for (int d = 0; d < DQK; d++) s = fmaf(sW[tid * DQK + d], qrow[d], s);
      sWt[tid] = s;
    }
    float cq = blockReduceSum256((tid < DQK) ? bk[tid] * qrow[tid] : 0.f, sRed, tid);

    float m = -3.0e38f;
    for (int c = tid; c < n; c += 256) {
      float dot = cq;
      const float* kr = key + (size_t)c * DIN;
      for (int d = 0; d < DIN; d++) dot = fmaf(sWt[d], kr[d], dot);
      float s = dot * 0.125f + brow[c];
      if (!(c >= rs0 && c < rs1)) s *= NEGM;
      m = fmaxf(m, s);
    }
    m = blockReduceMax256(m, sRed, tid);

    float dsum = 0.f;
    for (int c = tid; c < n; c += 256) {
      float dot = cq;
      const float* kr = key + (size_t)c * DIN;
      for (int d = 0; d < DIN; d++) dot = fmaf(sWt[d], kr[d], dot);
      float s = dot * 0.125f + brow[c];
      if (!(c >= rs0 && c < rs1)) s *= NEGM;
      dsum += expf(s - m);
    }
    float D = blockReduceSum256(dsum, sRed, tid);

    float o = 0.f;
    for (int base = rs0; base < rs1; base += 256) {
      int c = base + tid;
      float w = 0.f;
      if (c < rs1) {
        float dot = cq;
        const float* kr = key + (size_t)c * DIN;
        for (int d = 0; d < DIN; d++) dot = fmaf(sWt[d], kr[d], dot);
        float s = dot * 0.125f + brow[c];
        w = expf(s - m);
      }
      sRed[tid] = w;
      __syncthreads();
      int lim = min(256, rs1 - base);
      if (tid < DQK) {
        for (int cc = 0; cc < lim; cc++) {
          int c2 = base + cc;
          float vv = bv[tid];
          const float* vr = value + (size_t)c2 * DIN;
          for (int kk = 0; kk < DIN; kk++) vv = fmaf(vr[kk], Wv[kk * DQK + tid], vv);
          o = fmaf(sRed[cc], vv, o);
        }
      }
      __syncthreads();
    }
    if (tid < DQK) out[(size_t)row * DQK + tid] = o / D;
    __syncthreads();
  }
}

extern "C" void kernel_launch(void* const* d_in, const int* in_sizes, int n_in,
                              void* d_out, int out_size) {
  const float* query = (const float*)d_in[0];
  const float* key = (const float*)d_in[1];
  const float* value = (const float*)d_in[2];
  const float* bmat = (const float*)d_in[3];
  const int* ptr = (const int*)d_in[4];
  const float* Wq = (const float*)d_in[5];
  const float* bq = (const float*)d_in[6];
  const float* Wk = (const float*)d_in[7];
  const float* bk = (const float*)d_in[8];
  const float* Wv = (const float*)d_in[9];
  const float* bv = (const float*)d_in[10];
  float* out = (float*)d_out;

  int n = in_sizes[0] / DIN;
  int g = in_sizes[4] - 1;
  int nblk = (n + 31) / 32;

  size_t smB = (size_t)SMEM_FLOATS * sizeof(float);
  cudaFuncSetAttribute(fused_kernel, cudaFuncAttributeMaxDynamicSharedMemorySize, (int)smB);
  fused_kernel<<<nblk, 256, smB>>>(query, key, value, bmat, ptr, Wq, bq, Wk, bk,
                                   Wv, bv, out, n, g);
}